// round 5
// baseline (speedup 1.0000x reference)
#include <cuda_runtime.h>
#include <cuda_bf16.h>
#include <cstdint>

// LBP layer, fully fused, warp-strip, TWO s-columns per lane:
//   gray = dot(rgb, [0.2989, 0.587, 0.114])                (zero-padded outside)
//   s(y,x) = #{3x3 nbrs (incl. center): gray >= gray(y,x)} (s = 0 outside image)
//   lbp(y,x) = 1*s(y-1,x-1)+2*s(y-1,x)+4*s(y-1,x+1)
//            +128*s(y,x-1)           +8*s(y,x+1)
//            +64*s(y+1,x-1)+32*s(y+1,x)+16*s(y+1,x+1)
// Warp spans 64 s-columns (lane -> cols 2l, 2l+1), emits 62 outputs per row,
// rolls down 16 rows. s lives in registers; right-neighbors via 2 shfl_down.
// Fixed shapes: N=32, H=W=512, C=3. Output [N,H,W,1] fp32.

#define OUT_PW   62                    // output columns per block
#define RPW      16                    // output rows per warp
#define NWARPS   8
#define TILE_H   (RPW * NWARPS)        // 128
#define G_COLS   66                    // OUT_PW + 4 halo
#define G_STRIDE 66                    // even -> float2 ok
#define G_ROWS   (TILE_H + 4)          // 132
#define NTHREADS 256

__global__ __launch_bounds__(NTHREADS) void lbp_warp2_kernel(
    const float* __restrict__ in,   // [N, H, W, 3]
    float* __restrict__ out,        // [N, H, W, 1]
    int H, int W)
{
    __shared__ __align__(8) float g[G_ROWS * G_STRIDE];   // ~34.9 KB

    const int tid  = threadIdx.x;
    const int lane = tid & 31;
    const int wrp  = tid >> 5;
    const int bx = blockIdx.x, by = blockIdx.y, n = blockIdx.z;

    int x0 = bx * OUT_PW;
    if (x0 + OUT_PW > W) x0 = W - OUT_PW;     // overlap last block (dup stores ok)
    const int gx0 = x0 - 2;                   // even
    const int gy0 = by * TILE_H - 2;

    const float* __restrict__ base = in + (size_t)n * H * W * 3;

    // ---------------- Phase 1: RGB -> gray into smem (zero outside image) ----
    const bool colsInterior = (gx0 >= 0) && (gx0 + G_COLS <= W);
    if (colsInterior) {
        #pragma unroll 4
        for (int idx = tid; idx < G_ROWS * (G_COLS / 2); idx += NTHREADS) {
            const int r  = idx / (G_COLS / 2);
            const int pc = idx - r * (G_COLS / 2);
            const int gy = gy0 + r;
            float g0 = 0.0f, g1 = 0.0f;
            if ((unsigned)gy < (unsigned)H) {
                const int gx = gx0 + 2 * pc;
                const float2* p = (const float2*)(base + ((size_t)gy * W + gx) * 3);
                const float2 v0 = __ldg(p + 0);
                const float2 v1 = __ldg(p + 1);
                const float2 v2 = __ldg(p + 2);
                g0 = fmaf(0.2989f, v0.x, fmaf(0.587f, v0.y, 0.114f * v1.x));
                g1 = fmaf(0.2989f, v1.y, fmaf(0.587f, v2.x, 0.114f * v2.y));
            }
            *(float2*)&g[r * G_STRIDE + 2 * pc] = make_float2(g0, g1);
        }
    } else {
        #pragma unroll 4
        for (int idx = tid; idx < G_ROWS * G_COLS; idx += NTHREADS) {
            const int r = idx / G_COLS;
            const int c = idx - r * G_COLS;
            const int gy = gy0 + r;
            const int gx = gx0 + c;
            float v = 0.0f;
            if ((unsigned)gy < (unsigned)H && (unsigned)gx < (unsigned)W) {
                const float* p = base + ((size_t)gy * W + gx) * 3;
                v = fmaf(0.2989f, __ldg(p), fmaf(0.587f, __ldg(p + 1), 0.114f * __ldg(p + 2)));
            }
            g[r * G_STRIDE + c] = v;
        }
    }
    __syncthreads();

    // ------------- Phase 2+3 fused: two rolling s-columns per lane -----------
    // Lane's s cols (global): csA = x0-1+2*lane, csB = csA+1.
    // Gray cols needed (rel to gx0): 2*lane .. 2*lane+3.
    const int csA = x0 - 1 + 2 * lane;
    const bool colA = (unsigned)csA < (unsigned)W;
    const bool colB = (unsigned)(csA + 1) < (unsigned)W;
    const int r0 = by * TILE_H + wrp * RPW;

    const float* gp = &g[(wrp * RPW) * G_STRIDE + 2 * lane];

    float2 va = *(const float2*)(gp);     float2 va2 = *(const float2*)(gp + 2);
    float a0 = va.x, a1 = va.y, a2 = va2.x, a3 = va2.y;   gp += G_STRIDE;  // row r0-2
    float2 vb = *(const float2*)(gp);     float2 vb2 = *(const float2*)(gp + 2);
    float b0 = vb.x, b1 = vb.y, b2 = vb2.x, b3 = vb2.y;   gp += G_STRIDE;  // row r0-1

    // s rows: s2 = row yo-1, s1 = row yo (4 cols rel 2l..2l+3 each)
    float s2_0 = 0.f, s2_1 = 0.f, s2_2 = 0.f, s2_3 = 0.f;
    float s1_0 = 0.f, s1_1 = 0.f, s1_2 = 0.f, s1_3 = 0.f;

    const bool doStore = (lane <= 30);
    float* op = out + (size_t)n * H * W + (size_t)r0 * W + (x0 + 2 * lane);

    #pragma unroll
    for (int i = 0; i < RPW + 2; i++) {
        const float2 vt  = *(const float2*)(gp);
        const float2 vt2 = *(const float2*)(gp + 2);
        const float t0 = vt.x, t1 = vt.y, t2 = vt2.x, t3 = vt2.y;
        gp += G_STRIDE;

        const int ys = r0 - 1 + i;
        const bool rowOk = (unsigned)ys < (unsigned)H;

        // s at (ys, csA): center b1
        float cA = 1.0f;
        cA += (a0 >= b1) ? 1.0f : 0.0f;
        cA += (a1 >= b1) ? 1.0f : 0.0f;
        cA += (a2 >= b1) ? 1.0f : 0.0f;
        cA += (b0 >= b1) ? 1.0f : 0.0f;
        cA += (b2 >= b1) ? 1.0f : 0.0f;
        cA += (t0 >= b1) ? 1.0f : 0.0f;
        cA += (t1 >= b1) ? 1.0f : 0.0f;
        cA += (t2 >= b1) ? 1.0f : 0.0f;

        // s at (ys, csB): center b2
        float cB = 1.0f;
        cB += (a1 >= b2) ? 1.0f : 0.0f;
        cB += (a2 >= b2) ? 1.0f : 0.0f;
        cB += (a3 >= b2) ? 1.0f : 0.0f;
        cB += (b1 >= b2) ? 1.0f : 0.0f;
        cB += (b3 >= b2) ? 1.0f : 0.0f;
        cB += (t1 >= b2) ? 1.0f : 0.0f;
        cB += (t2 >= b2) ? 1.0f : 0.0f;
        cB += (t3 >= b2) ? 1.0f : 0.0f;

        const float sa = (rowOk && colA) ? cA : 0.0f;   // zero-pad s
        const float sb = (rowOk && colB) ? cB : 0.0f;

        const float na = __shfl_down_sync(0xffffffffu, sa, 1);  // s rel 2l+2
        const float nb = __shfl_down_sync(0xffffffffu, sb, 1);  // s rel 2l+3

        if (i >= 2) {
            // emit row yo = ys-1, cols csA+1 (=x0+2l) and csA+2
            float v0 = s2_0;
            v0 = fmaf(  2.0f, s2_1, v0);
            v0 = fmaf(  4.0f, s2_2, v0);
            v0 = fmaf(128.0f, s1_0, v0);
            v0 = fmaf(  8.0f, s1_2, v0);
            v0 = fmaf( 64.0f, sa,   v0);
            v0 = fmaf( 32.0f, sb,   v0);
            v0 = fmaf( 16.0f, na,   v0);

            float v1 = s2_1;
            v1 = fmaf(  2.0f, s2_2, v1);
            v1 = fmaf(  4.0f, s2_3, v1);
            v1 = fmaf(128.0f, s1_1, v1);
            v1 = fmaf(  8.0f, s1_3, v1);
            v1 = fmaf( 64.0f, sb,   v1);
            v1 = fmaf( 32.0f, na,   v1);
            v1 = fmaf( 16.0f, nb,   v1);

            if (doStore) *(float2*)op = make_float2(v0, v1);
            op += W;
        }

        s2_0 = s1_0; s2_1 = s1_1; s2_2 = s1_2; s2_3 = s1_3;
        s1_0 = sa;   s1_1 = sb;   s1_2 = na;   s1_3 = nb;
        a0 = b0; a1 = b1; a2 = b2; a3 = b3;
        b0 = t0; b1 = t1; b2 = t2; b3 = t3;
    }
}

extern "C" void kernel_launch(void* const* d_in, const int* in_sizes, int n_in,
                              void* d_out, int out_size)
{
    const float* in = (const float*)d_in[0];
    float* out = (float*)d_out;

    const int H = 512, W = 512;
    const int N = in_sizes[0] / (H * W * 3);

    dim3 grid((W + OUT_PW - 1) / OUT_PW, H / TILE_H, N);   // 9 x 4 x 32
    lbp_warp2_kernel<<<grid, NTHREADS>>>(in, out, H, W);
}

// round 6
// speedup vs baseline: 1.2620x; 1.2620x over previous
#include <cuda_runtime.h>
#include <cuda_bf16.h>
#include <cstdint>

// LBP layer, fully fused, warp-strip, two s-columns per lane, predicated adds.
//   gray = dot(rgb, [0.2989, 0.587, 0.114])                (zero-padded outside)
//   s(y,x) = #{3x3 nbrs (incl. center): gray >= gray(y,x)} (s = 0 outside image)
//   lbp(y,x) = 1*s(y-1,x-1)+2*s(y-1,x)+4*s(y-1,x+1)
//            +128*s(y,x-1)           +8*s(y,x+1)
//            +64*s(y+1,x-1)+32*s(y+1,x)+16*s(y+1,x+1)
// Warp spans 64 s-columns (lane -> cols 2l, 2l+1), emits 62 outputs per row,
// rolls down 8 rows. s lives in registers; right-neighbors via 2 shfl_down.
// 128-thread blocks (4 warps stacked vertically), 4608 blocks total.
// Fixed shapes: N=32, H=W=512, C=3. Output [N,H,W,1] fp32.

#define OUT_PW   62                    // output columns per block
#define RPW      8                     // output rows per warp
#define NWARPS   4
#define TILE_H   (RPW * NWARPS)        // 32
#define G_COLS   66                    // OUT_PW + 4 halo
#define G_STRIDE 66                    // even -> float2 ok
#define G_ROWS   (TILE_H + 4)          // 36
#define NTHREADS 128

__global__ __launch_bounds__(NTHREADS, 12) void lbp_warp2_kernel(
    const float* __restrict__ in,   // [N, H, W, 3]
    float* __restrict__ out,        // [N, H, W, 1]
    int H, int W)
{
    __shared__ __align__(8) float g[G_ROWS * G_STRIDE];   // 9.5 KB

    const int tid  = threadIdx.x;
    const int lane = tid & 31;
    const int wrp  = tid >> 5;
    const int bx = blockIdx.x, by = blockIdx.y, n = blockIdx.z;

    int x0 = bx * OUT_PW;
    if (x0 + OUT_PW > W) x0 = W - OUT_PW;     // overlap last block (dup stores ok)
    const int gx0 = x0 - 2;                   // even
    const int gy0 = by * TILE_H - 2;

    const float* __restrict__ base = in + (size_t)n * H * W * 3;

    // ---------------- Phase 1: RGB -> gray into smem (zero outside image) ----
    const bool colsInterior = (gx0 >= 0) && (gx0 + G_COLS <= W);
    if (colsInterior) {
        #pragma unroll 4
        for (int idx = tid; idx < G_ROWS * (G_COLS / 2); idx += NTHREADS) {
            const int r  = idx / (G_COLS / 2);
            const int pc = idx - r * (G_COLS / 2);
            const int gy = gy0 + r;
            float g0 = 0.0f, g1 = 0.0f;
            if ((unsigned)gy < (unsigned)H) {
                const int gx = gx0 + 2 * pc;
                const float2* p = (const float2*)(base + ((size_t)gy * W + gx) * 3);
                const float2 v0 = __ldg(p + 0);
                const float2 v1 = __ldg(p + 1);
                const float2 v2 = __ldg(p + 2);
                g0 = fmaf(0.2989f, v0.x, fmaf(0.587f, v0.y, 0.114f * v1.x));
                g1 = fmaf(0.2989f, v1.y, fmaf(0.587f, v2.x, 0.114f * v2.y));
            }
            *(float2*)&g[r * G_STRIDE + 2 * pc] = make_float2(g0, g1);
        }
    } else {
        #pragma unroll 4
        for (int idx = tid; idx < G_ROWS * G_COLS; idx += NTHREADS) {
            const int r = idx / G_COLS;
            const int c = idx - r * G_COLS;
            const int gy = gy0 + r;
            const int gx = gx0 + c;
            float v = 0.0f;
            if ((unsigned)gy < (unsigned)H && (unsigned)gx < (unsigned)W) {
                const float* p = base + ((size_t)gy * W + gx) * 3;
                v = fmaf(0.2989f, __ldg(p), fmaf(0.587f, __ldg(p + 1), 0.114f * __ldg(p + 2)));
            }
            g[r * G_STRIDE + c] = v;
        }
    }
    __syncthreads();

    // ------------- Phase 2+3 fused: two rolling s-columns per lane -----------
    // Lane's s cols (global): csA = x0-1+2*lane, csB = csA+1.
    const int csA = x0 - 1 + 2 * lane;
    const bool colA = (unsigned)csA < (unsigned)W;
    const bool colB = (unsigned)(csA + 1) < (unsigned)W;
    const int r0 = by * TILE_H + wrp * RPW;

    const float* gp = &g[(wrp * RPW) * G_STRIDE + 2 * lane];

    float2 va = *(const float2*)(gp);     float2 va2 = *(const float2*)(gp + 2);
    float a0 = va.x, a1 = va.y, a2 = va2.x, a3 = va2.y;   gp += G_STRIDE;  // row r0-2
    float2 vb = *(const float2*)(gp);     float2 vb2 = *(const float2*)(gp + 2);
    float b0 = vb.x, b1 = vb.y, b2 = vb2.x, b3 = vb2.y;   gp += G_STRIDE;  // row r0-1

    float s2_0 = 0.f, s2_1 = 0.f, s2_2 = 0.f, s2_3 = 0.f;
    float s1_0 = 0.f, s1_1 = 0.f, s1_2 = 0.f, s1_3 = 0.f;

    const bool doStore = (lane <= 30);
    float* op = out + (size_t)n * H * W + (size_t)r0 * W + (x0 + 2 * lane);

    #pragma unroll
    for (int i = 0; i < RPW + 2; i++) {
        const float2 vt  = *(const float2*)(gp);
        const float2 vt2 = *(const float2*)(gp + 2);
        const float t0 = vt.x, t1 = vt.y, t2 = vt2.x, t3 = vt2.y;
        gp += G_STRIDE;

        const int ys = r0 - 1 + i;
        const bool rowOk = (unsigned)ys < (unsigned)H;

        // s at (ys, csA): center b1 (predicated single-inst adds, 2 indep chains)
        float cA = 1.0f, cB = 1.0f;
        if (a0 >= b1) cA += 1.0f;
        if (a1 >= b2) cB += 1.0f;
        if (a1 >= b1) cA += 1.0f;
        if (a2 >= b2) cB += 1.0f;
        if (a2 >= b1) cA += 1.0f;
        if (a3 >= b2) cB += 1.0f;
        if (b0 >= b1) cA += 1.0f;
        if (b1 >= b2) cB += 1.0f;
        if (b2 >= b1) cA += 1.0f;
        if (b3 >= b2) cB += 1.0f;
        if (t0 >= b1) cA += 1.0f;
        if (t1 >= b2) cB += 1.0f;
        if (t1 >= b1) cA += 1.0f;
        if (t2 >= b2) cB += 1.0f;
        if (t2 >= b1) cA += 1.0f;
        if (t3 >= b2) cB += 1.0f;

        const float sa = (rowOk && colA) ? cA : 0.0f;   // zero-pad s
        const float sb = (rowOk && colB) ? cB : 0.0f;

        const float na = __shfl_down_sync(0xffffffffu, sa, 1);  // s rel 2l+2
        const float nb = __shfl_down_sync(0xffffffffu, sb, 1);  // s rel 2l+3

        if (i >= 2) {
            // emit row yo = ys-1, cols x0+2*lane and x0+2*lane+1
            float v0 = s2_0;
            v0 = fmaf(  2.0f, s2_1, v0);
            v0 = fmaf(  4.0f, s2_2, v0);
            v0 = fmaf(128.0f, s1_0, v0);
            v0 = fmaf(  8.0f, s1_2, v0);
            v0 = fmaf( 64.0f, sa,   v0);
            v0 = fmaf( 32.0f, sb,   v0);
            v0 = fmaf( 16.0f, na,   v0);

            float v1 = s2_1;
            v1 = fmaf(  2.0f, s2_2, v1);
            v1 = fmaf(  4.0f, s2_3, v1);
            v1 = fmaf(128.0f, s1_1, v1);
            v1 = fmaf(  8.0f, s1_3, v1);
            v1 = fmaf( 64.0f, sb,   v1);
            v1 = fmaf( 32.0f, na,   v1);
            v1 = fmaf( 16.0f, nb,   v1);

            if (doStore) *(float2*)op = make_float2(v0, v1);
            op += W;
        }

        s2_0 = s1_0; s2_1 = s1_1; s2_2 = s1_2; s2_3 = s1_3;
        s1_0 = sa;   s1_1 = sb;   s1_2 = na;   s1_3 = nb;
        a0 = b0; a1 = b1; a2 = b2; a3 = b3;
        b0 = t0; b1 = t1; b2 = t2; b3 = t3;
    }
}

extern "C" void kernel_launch(void* const* d_in, const int* in_sizes, int n_in,
                              void* d_out, int out_size)
{
    const float* in = (const float*)d_in[0];
    float* out = (float*)d_out;

    const int H = 512, W = 512;
    const int N = in_sizes[0] / (H * W * 3);

    dim3 grid((W + OUT_PW - 1) / OUT_PW, H / TILE_H, N);   // 9 x 16 x 32 = 4608
    lbp_warp2_kernel<<<grid, NTHREADS>>>(in, out, H, W);
}